// round 7
// baseline (speedup 1.0000x reference)
#include <cuda_runtime.h>
#include <cuda_fp16.h>
#include <cstdint>

#define NUM_USERS 100000
#define NUM_ITEMS 100000
#define N_NODES   200000
#define EMB       64
#define N_EDGES   3200000
#define SCAN_BLK  1024
#define N_SCAN_BLKS ((N_NODES + SCAN_BLK - 1) / SCAN_BLK)   // 196

// ---------------------------------------------------------------------------
// Static device scratch (allocation-free per harness rules).
// Intermediate layer outputs in fp16: halves the dominant random-read traffic.
// ---------------------------------------------------------------------------
__device__ __half2 g_b0[(size_t)N_NODES * 32];    // layer-1 output (25.6 MB)
__device__ __half2 g_b1[(size_t)N_NODES * 32];    // layer-2 output (25.6 MB)
__device__ int2    g_csr[N_EDGES];                // (col, w-bits) grouped by row
__device__ int     g_cnt[N_NODES];
__device__ int     g_rowstart[N_NODES + 1];
__device__ int     g_cursor[N_NODES];
__device__ int     g_blksums[N_SCAN_BLKS];

// ---------------------------------------------------------------------------
// CSR build: zero -> count -> scan(3 stages, all parallel) -> fill
// ---------------------------------------------------------------------------
__global__ void k_zero()
{
    int i = blockIdx.x * blockDim.x + threadIdx.x;
    if (i < N_NODES) g_cnt[i] = 0;
}

__global__ void __launch_bounds__(256) k_count(const int* __restrict__ row)
{
    int e = blockIdx.x * blockDim.x + threadIdx.x;
    if (e < N_EDGES) atomicAdd(&g_cnt[__ldg(row + e)], 1);
}

__global__ void __launch_bounds__(SCAN_BLK) k_scan1()
{
    __shared__ int s[SCAN_BLK];
    int t = threadIdx.x;
    int i = blockIdx.x * SCAN_BLK + t;
    int v = (i < N_NODES) ? g_cnt[i] : 0;
    s[t] = v;
    __syncthreads();
    #pragma unroll
    for (int off = 1; off < SCAN_BLK; off <<= 1) {
        int add = (t >= off) ? s[t - off] : 0;
        __syncthreads();
        s[t] += add;
        __syncthreads();
    }
    if (i < N_NODES) g_rowstart[i] = s[t] - v;           // exclusive in-block
    if (t == SCAN_BLK - 1) g_blksums[blockIdx.x] = s[t]; // block total
}

// Parallel scan over the 196 block sums (replaces 11.3us serial version).
__global__ void __launch_bounds__(256) k_scan2()
{
    __shared__ int s[256];
    int t = threadIdx.x;
    int v = (t < N_SCAN_BLKS) ? g_blksums[t] : 0;
    s[t] = v;
    __syncthreads();
    #pragma unroll
    for (int off = 1; off < 256; off <<= 1) {
        int add = (t >= off) ? s[t - off] : 0;
        __syncthreads();
        s[t] += add;
        __syncthreads();
    }
    if (t < N_SCAN_BLKS) g_blksums[t] = s[t] - v;        // exclusive
}

__global__ void k_scan3()
{
    int i = blockIdx.x * blockDim.x + threadIdx.x;
    if (i < N_NODES) {
        int v = g_rowstart[i] + g_blksums[i >> 10];
        g_rowstart[i] = v;
        g_cursor[i]   = v;
    }
    if (i == 0) g_rowstart[N_NODES] = N_EDGES;
}

__global__ void __launch_bounds__(256)
k_fill(const int* __restrict__ row, const int* __restrict__ col,
       const float* __restrict__ w)
{
    int e = blockIdx.x * blockDim.x + threadIdx.x;
    if (e >= N_EDGES) return;
    int r   = __ldg(row + e);
    int pos = atomicAdd(&g_cursor[r], 1);
    g_csr[pos] = make_int2(__ldg(col + e), __float_as_int(__ldg(w + e)));
}

// ---------------------------------------------------------------------------
// Gather SpMM: one warp per destination row.
//   L0: src = fp32 user/item (float2/lane, 256B/edge) -> b0 (fp16) + out=l1
//   L1: src = b0 fp16 (half2/lane, 128B/edge)         -> b1 (fp16)
//   L2: src = b1 fp16                                  -> out = (l1+l2+l3)/3
// 8-edge batches for MLP=8 independent gathers per warp iteration.
// ---------------------------------------------------------------------------
template<int LAYER>
__device__ __forceinline__ float2 ld_src(int c, int lane,
                                         const float2* __restrict__ user,
                                         const float2* __restrict__ item)
{
    if (LAYER == 0) {
        return (c < NUM_USERS)
            ? __ldg(user + (size_t)c * 32 + lane)
            : __ldg(item + (size_t)(c - NUM_USERS) * 32 + lane);
    } else {
        const __half2* b = (LAYER == 1) ? g_b0 : g_b1;
        return __half22float2(b[(size_t)c * 32 + lane]);
    }
}

template<int LAYER>
__global__ void __launch_bounds__(256)
k_gather(const float2* __restrict__ user, const float2* __restrict__ item,
         float2* __restrict__ out)
{
    int gwarp = (blockIdx.x * blockDim.x + threadIdx.x) >> 5;
    int lane  = threadIdx.x & 31;
    if (gwarp >= N_NODES) return;
    const int start = __ldg(&g_rowstart[gwarp]);
    const int end   = __ldg(&g_rowstart[gwarp + 1]);

    float ax = 0.f, ay = 0.f;
    int j = start;
    for (; j + 8 <= end; j += 8) {
        int2 m[8];
        #pragma unroll
        for (int k = 0; k < 8; ++k) m[k] = __ldg(&g_csr[j + k]);
        float2 v[8];
        #pragma unroll
        for (int k = 0; k < 8; ++k) v[k] = ld_src<LAYER>(m[k].x, lane, user, item);
        #pragma unroll
        for (int k = 0; k < 8; ++k) {
            float w = __int_as_float(m[k].y);
            ax += w * v[k].x;
            ay += w * v[k].y;
        }
    }
    if (j + 4 <= end) {
        int2 m[4];
        #pragma unroll
        for (int k = 0; k < 4; ++k) m[k] = __ldg(&g_csr[j + k]);
        float2 v[4];
        #pragma unroll
        for (int k = 0; k < 4; ++k) v[k] = ld_src<LAYER>(m[k].x, lane, user, item);
        #pragma unroll
        for (int k = 0; k < 4; ++k) {
            float w = __int_as_float(m[k].y);
            ax += w * v[k].x;
            ay += w * v[k].y;
        }
        j += 4;
    }
    for (; j < end; ++j) {
        int2 m = __ldg(&g_csr[j]);
        float2 v = ld_src<LAYER>(m.x, lane, user, item);
        float w = __int_as_float(m.y);
        ax += w * v.x;
        ay += w * v.y;
    }

    const size_t oidx = (size_t)gwarp * 32 + lane;
    if (LAYER == 0) {
        g_b0[oidx] = __floats2half2_rn(ax, ay);
        out[oidx]  = make_float2(ax, ay);              // l1, fp32, undivided
    } else if (LAYER == 1) {
        g_b1[oidx] = __floats2half2_rn(ax, ay);
    } else {
        float2 l1 = out[oidx];
        float2 l2 = __half22float2(g_b1[oidx]);
        const float inv3 = 1.0f / 3.0f;
        out[oidx] = make_float2((l1.x + l2.x + ax) * inv3,
                                (l1.y + l2.y + ay) * inv3);
    }
}

// ---------------------------------------------------------------------------
// Launch. Inputs (metadata order):
//   d_in[0] user_emb f32 [100000*64]   d_in[1] item_emb f32 [100000*64]
//   d_in[2] edge_w   f32 [3.2M]        d_in[3] edge_row i32   d_in[4] edge_col i32
// d_out: f32 [200000*64] = (l1+l2+l3)/3.
// ---------------------------------------------------------------------------
extern "C" void kernel_launch(void* const* d_in, const int* in_sizes, int n_in,
                              void* d_out, int out_size)
{
    const float2* user = (const float2*)d_in[0];
    const float2* item = (const float2*)d_in[1];
    const float*  ew   = (const float*)d_in[2];
    const int*    erow = (const int*)d_in[3];
    const int*    ecol = (const int*)d_in[4];
    float2*       out  = (float2*)d_out;

    const int BLK = 256;
    const int grid_nodes  = (N_NODES + BLK - 1) / BLK;        // 782
    const int grid_edges  = (N_EDGES + BLK - 1) / BLK;        // 12500
    const int grid_gather = (N_NODES * 32 + BLK - 1) / BLK;   // 25000 (warp/row)

    // CSR build (once; reused by all 3 layers)
    k_zero <<<grid_nodes, BLK>>>();
    k_count<<<grid_edges, BLK>>>(erow);
    k_scan1<<<N_SCAN_BLKS, SCAN_BLK>>>();
    k_scan2<<<1, 256>>>();
    k_scan3<<<grid_nodes, BLK>>>();
    k_fill <<<grid_edges, BLK>>>(erow, ecol, ew);

    // 3 pull-style SpMM layers
    k_gather<0><<<grid_gather, BLK>>>(user, item, out);
    k_gather<1><<<grid_gather, BLK>>>(user, item, out);
    k_gather<2><<<grid_gather, BLK>>>(user, item, out);
}

// round 8
// speedup vs baseline: 1.1340x; 1.1340x over previous
#include <cuda_runtime.h>
#include <cstdint>

#define NUM_USERS 100000
#define NUM_ITEMS 100000
#define N_NODES   200000
#define EMB       64
#define N_EDGES   3200000
#define CSR_CAP   (N_EDGES + N_NODES)     // even-padded rows: <= E + V entries
#define SCAN_BLK  1024
#define N_SCAN_BLKS ((N_NODES + SCAN_BLK - 1) / SCAN_BLK)   // 196

// ---------------------------------------------------------------------------
// Static device scratch (allocation-free per harness rules). fp32 buffers.
// ---------------------------------------------------------------------------
__device__ float g_buf0[(size_t)N_NODES * EMB];   // layer-1 output (51.2 MB)
__device__ float g_buf1[(size_t)N_NODES * EMB];   // layer-2 output (51.2 MB)
__device__ __align__(16) int2 g_csr[CSR_CAP];     // (col, w-bits), rows even-padded
__device__ int g_cnt[N_NODES];                    // actual degree
__device__ int g_rowstart[N_NODES];               // PADDED exclusive offsets
__device__ int g_cursor[N_NODES];
__device__ int g_blksums[N_SCAN_BLKS];

// ---------------------------------------------------------------------------
// CSR build: zero -> count -> padded scan (3 stages) -> fill (+pad slots)
// ---------------------------------------------------------------------------
__global__ void k_zero()
{
    int i = blockIdx.x * blockDim.x + threadIdx.x;
    if (i < N_NODES) g_cnt[i] = 0;
}

__global__ void __launch_bounds__(256) k_count(const int* __restrict__ row)
{
    int e = blockIdx.x * blockDim.x + threadIdx.x;
    if (e < N_EDGES) atomicAdd(&g_cnt[__ldg(row + e)], 1);
}

// Scan of PADDED counts p_i = (c_i+1)&~1  (rows start 16B-aligned in g_csr).
__global__ void __launch_bounds__(SCAN_BLK) k_scan1()
{
    __shared__ int s[SCAN_BLK];
    int t = threadIdx.x;
    int i = blockIdx.x * SCAN_BLK + t;
    int c = (i < N_NODES) ? g_cnt[i] : 0;
    int v = (c + 1) & ~1;                 // padded degree
    s[t] = v;
    __syncthreads();
    #pragma unroll
    for (int off = 1; off < SCAN_BLK; off <<= 1) {
        int add = (t >= off) ? s[t - off] : 0;
        __syncthreads();
        s[t] += add;
        __syncthreads();
    }
    if (i < N_NODES) g_rowstart[i] = s[t] - v;           // exclusive in-block
    if (t == SCAN_BLK - 1) g_blksums[blockIdx.x] = s[t]; // block total
}

__global__ void __launch_bounds__(256) k_scan2()
{
    __shared__ int s[256];
    int t = threadIdx.x;
    int v = (t < N_SCAN_BLKS) ? g_blksums[t] : 0;
    s[t] = v;
    __syncthreads();
    #pragma unroll
    for (int off = 1; off < 256; off <<= 1) {
        int add = (t >= off) ? s[t - off] : 0;
        __syncthreads();
        s[t] += add;
        __syncthreads();
    }
    if (t < N_SCAN_BLKS) g_blksums[t] = s[t] - v;        // exclusive
}

// Finalize offsets; init cursors; write the w=0 pad slot for odd-degree rows.
__global__ void k_scan3()
{
    int i = blockIdx.x * blockDim.x + threadIdx.x;
    if (i >= N_NODES) return;
    int v = g_rowstart[i] + g_blksums[i >> 10];
    g_rowstart[i] = v;
    g_cursor[i]   = v;
    int c = g_cnt[i];
    if (c & 1) g_csr[v + c] = make_int2(0, 0);           // col=0, w=0 (harmless)
}

__global__ void __launch_bounds__(256)
k_fill(const int* __restrict__ row, const int* __restrict__ col,
       const float* __restrict__ w)
{
    int e = blockIdx.x * blockDim.x + threadIdx.x;
    if (e >= N_EDGES) return;
    int r   = __ldg(row + e);
    int pos = atomicAdd(&g_cursor[r], 1);
    g_csr[pos] = make_int2(__ldg(col + e), __float_as_int(__ldg(w + e)));
}

// ---------------------------------------------------------------------------
// Gather SpMM: 2 rows per warp, 16 lanes x float4 per row.
//   src LDG:  1 LDG.128 warp-instr per 2 edges   (0.5 / edge)
//   meta LDG: 1 int4 (2 edges) per half-warp; both halves in one warp-instr
//             -> 0.25 / edge.   Total 0.75 LDG/edge vs 2.0 before.
// Rows even-padded: all tails handled in 2-edge (one int4) granularity.
// ---------------------------------------------------------------------------
template<int LAYER>
__device__ __forceinline__ float4 ld_src(int c, int sub,
                                         const float4* __restrict__ user,
                                         const float4* __restrict__ item)
{
    if (LAYER == 0) {
        return (c < NUM_USERS)
            ? __ldg(user + (size_t)c * 16 + sub)
            : __ldg(item + (size_t)(c - NUM_USERS) * 16 + sub);
    } else {
        const float4* b = (LAYER == 1)
            ? reinterpret_cast<const float4*>(g_buf0)
            : reinterpret_cast<const float4*>(g_buf1);
        return __ldg(b + (size_t)c * 16 + sub);
    }
}

template<int LAYER>
__global__ void __launch_bounds__(256)
k_gather(const float4* __restrict__ user, const float4* __restrict__ item,
         float4* __restrict__ out)
{
    int tid  = blockIdx.x * blockDim.x + threadIdx.x;
    int gw   = tid >> 5;
    int lane = threadIdx.x & 31;
    int half = lane >> 4;
    int sub  = lane & 15;
    int row  = gw * 2 + half;
    if (row >= N_NODES) return;

    const int start = __ldg(&g_rowstart[row]);
    const int cnt   = __ldg(&g_cnt[row]);
    const int pend  = start + ((cnt + 1) & ~1);          // padded end (even span)
    const int4* csr4 = reinterpret_cast<const int4*>(g_csr);

    float ax = 0.f, ay = 0.f, az = 0.f, aw = 0.f;
    int j = start;

    // 8-edge batches: 4 int4 meta + 8 float4 src loads in flight per half.
    for (; j + 8 <= pend; j += 8) {
        int4 m0 = __ldg(csr4 + (j >> 1) + 0);
        int4 m1 = __ldg(csr4 + (j >> 1) + 1);
        int4 m2 = __ldg(csr4 + (j >> 1) + 2);
        int4 m3 = __ldg(csr4 + (j >> 1) + 3);
        float4 v0 = ld_src<LAYER>(m0.x, sub, user, item);
        float4 v1 = ld_src<LAYER>(m0.z, sub, user, item);
        float4 v2 = ld_src<LAYER>(m1.x, sub, user, item);
        float4 v3 = ld_src<LAYER>(m1.z, sub, user, item);
        float4 v4 = ld_src<LAYER>(m2.x, sub, user, item);
        float4 v5 = ld_src<LAYER>(m2.z, sub, user, item);
        float4 v6 = ld_src<LAYER>(m3.x, sub, user, item);
        float4 v7 = ld_src<LAYER>(m3.z, sub, user, item);
        float w0 = __int_as_float(m0.y), w1 = __int_as_float(m0.w);
        float w2 = __int_as_float(m1.y), w3 = __int_as_float(m1.w);
        float w4 = __int_as_float(m2.y), w5 = __int_as_float(m2.w);
        float w6 = __int_as_float(m3.y), w7 = __int_as_float(m3.w);
        ax += w0*v0.x; ay += w0*v0.y; az += w0*v0.z; aw += w0*v0.w;
        ax += w1*v1.x; ay += w1*v1.y; az += w1*v1.z; aw += w1*v1.w;
        ax += w2*v2.x; ay += w2*v2.y; az += w2*v2.z; aw += w2*v2.w;
        ax += w3*v3.x; ay += w3*v3.y; az += w3*v3.z; aw += w3*v3.w;
        ax += w4*v4.x; ay += w4*v4.y; az += w4*v4.z; aw += w4*v4.w;
        ax += w5*v5.x; ay += w5*v5.y; az += w5*v5.z; aw += w5*v5.w;
        ax += w6*v6.x; ay += w6*v6.y; az += w6*v6.z; aw += w6*v6.w;
        ax += w7*v7.x; ay += w7*v7.y; az += w7*v7.z; aw += w7*v7.w;
    }
    if (j + 4 <= pend) {
        int4 m0 = __ldg(csr4 + (j >> 1) + 0);
        int4 m1 = __ldg(csr4 + (j >> 1) + 1);
        float4 v0 = ld_src<LAYER>(m0.x, sub, user, item);
        float4 v1 = ld_src<LAYER>(m0.z, sub, user, item);
        float4 v2 = ld_src<LAYER>(m1.x, sub, user, item);
        float4 v3 = ld_src<LAYER>(m1.z, sub, user, item);
        float w0 = __int_as_float(m0.y), w1 = __int_as_float(m0.w);
        float w2 = __int_as_float(m1.y), w3 = __int_as_float(m1.w);
        ax += w0*v0.x; ay += w0*v0.y; az += w0*v0.z; aw += w0*v0.w;
        ax += w1*v1.x; ay += w1*v1.y; az += w1*v1.z; aw += w1*v1.w;
        ax += w2*v2.x; ay += w2*v2.y; az += w2*v2.z; aw += w2*v2.w;
        ax += w3*v3.x; ay += w3*v3.y; az += w3*v3.z; aw += w3*v3.w;
        j += 4;
    }
    if (j + 2 <= pend) {
        int4 m = __ldg(csr4 + (j >> 1));
        float4 v0 = ld_src<LAYER>(m.x, sub, user, item);
        float4 v1 = ld_src<LAYER>(m.z, sub, user, item);
        float w0 = __int_as_float(m.y), w1 = __int_as_float(m.w);
        ax += w0*v0.x; ay += w0*v0.y; az += w0*v0.z; aw += w0*v0.w;
        ax += w1*v1.x; ay += w1*v1.y; az += w1*v1.z; aw += w1*v1.w;
    }

    const size_t o = (size_t)row * 16 + sub;
    float4 res = make_float4(ax, ay, az, aw);
    if (LAYER == 0) {
        reinterpret_cast<float4*>(g_buf0)[o] = res;      // layer-1, src of L1
        out[o] = res;                                    // l1 undivided
    } else if (LAYER == 1) {
        reinterpret_cast<float4*>(g_buf1)[o] = res;      // layer-2, src of L2
    } else {
        float4 l1 = out[o];
        float4 l2 = reinterpret_cast<const float4*>(g_buf1)[o];
        const float inv3 = 1.0f / 3.0f;
        out[o] = make_float4((l1.x + l2.x + ax) * inv3,
                             (l1.y + l2.y + ay) * inv3,
                             (l1.z + l2.z + az) * inv3,
                             (l1.w + l2.w + aw) * inv3);
    }
}

// ---------------------------------------------------------------------------
// Launch. Inputs (metadata order):
//   d_in[0] user_emb f32 [100000*64]   d_in[1] item_emb f32 [100000*64]
//   d_in[2] edge_w   f32 [3.2M]        d_in[3] edge_row i32   d_in[4] edge_col i32
// d_out: f32 [200000*64] = (l1+l2+l3)/3.
// ---------------------------------------------------------------------------
extern "C" void kernel_launch(void* const* d_in, const int* in_sizes, int n_in,
                              void* d_out, int out_size)
{
    const float4* user = (const float4*)d_in[0];
    const float4* item = (const float4*)d_in[1];
    const float*  ew   = (const float*)d_in[2];
    const int*    erow = (const int*)d_in[3];
    const int*    ecol = (const int*)d_in[4];
    float4*       out  = (float4*)d_out;

    const int BLK = 256;
    const int grid_nodes  = (N_NODES + BLK - 1) / BLK;            // 782
    const int grid_edges  = (N_EDGES + BLK - 1) / BLK;            // 12500
    const int grid_gather = ((N_NODES / 2) * 32 + BLK - 1) / BLK; // 12500 (warp/2rows)

    // CSR build (once; reused by all 3 layers)
    k_zero <<<grid_nodes, BLK>>>();
    k_count<<<grid_edges, BLK>>>(erow);
    k_scan1<<<N_SCAN_BLKS, SCAN_BLK>>>();
    k_scan2<<<1, 256>>>();
    k_scan3<<<grid_nodes, BLK>>>();
    k_fill <<<grid_edges, BLK>>>(erow, ecol, ew);

    // 3 pull-style SpMM layers
    k_gather<0><<<grid_gather, BLK>>>(user, item, out);
    k_gather<1><<<grid_gather, BLK>>>(user, item, out);
    k_gather<2><<<grid_gather, BLK>>>(user, item, out);
}

// round 10
// speedup vs baseline: 1.5191x; 1.3396x over previous
#include <cuda_runtime.h>
#include <cuda_fp16.h>
#include <cstdint>

#define NUM_USERS 100000
#define NUM_ITEMS 100000
#define N_NODES   200000
#define EMB       64
#define N_EDGES   3200000
#define VEC_TOTAL (N_NODES * (EMB / 4))   // 3.2M float4 per fp32 node-buffer
#define CSR_CAP   (N_EDGES + N_NODES)     // even-padded rows: <= E + V entries
#define SCAN_BLK  1024
#define N_SCAN_BLKS ((N_NODES + SCAN_BLK - 1) / SCAN_BLK)   // 196

// ---------------------------------------------------------------------------
// Static device scratch (allocation-free per harness rules).
// fp16 node buffers (25.6 MB each): halves the dominant random-read traffic
// while keeping the LDG warp-instruction count of the R8 layout.
// ---------------------------------------------------------------------------
__device__ __align__(16) uint2 g_src[(size_t)N_NODES * 16];  // fp16 ego (l0 input)
__device__ __align__(16) uint2 g_l1h[(size_t)N_NODES * 16];  // fp16 layer-1 out
__device__ __align__(16) uint2 g_l2h[(size_t)N_NODES * 16];  // fp16 layer-2 out
__device__ __align__(16) int2  g_csr[CSR_CAP];  // (col, w-bits), rows even-padded
__device__ int2 g_hdr[N_NODES];                 // (rowstart, cnt) packed
__device__ int  g_cnt[N_NODES];
__device__ int  g_rowstart[N_NODES];
__device__ int  g_cursor[N_NODES];
__device__ int  g_blksums[N_SCAN_BLKS];

// ---------------------------------------------------------------------------
// Init: fp16-convert concat(user,item) into g_src.
// ---------------------------------------------------------------------------
__global__ void __launch_bounds__(256)
k_init(const float4* __restrict__ user, const float4* __restrict__ item)
{
    int i = blockIdx.x * blockDim.x + threadIdx.x;
    if (i >= VEC_TOTAL) return;
    const int usz = NUM_USERS * (EMB / 4);
    float4 v = (i < usz) ? __ldg(user + i) : __ldg(item + (i - usz));
    __half2 h0 = __floats2half2_rn(v.x, v.y);
    __half2 h1 = __floats2half2_rn(v.z, v.w);
    uint2 u;
    u.x = *reinterpret_cast<unsigned*>(&h0);
    u.y = *reinterpret_cast<unsigned*>(&h1);
    g_src[i] = u;
}

// ---------------------------------------------------------------------------
// CSR build: zero -> count -> padded scan (3 stages) -> fill (+pad slots)
// ---------------------------------------------------------------------------
__global__ void k_zero()
{
    int i = blockIdx.x * blockDim.x + threadIdx.x;
    if (i < N_NODES) g_cnt[i] = 0;
}

__global__ void __launch_bounds__(256) k_count(const int* __restrict__ row)
{
    int e = blockIdx.x * blockDim.x + threadIdx.x;
    if (e < N_EDGES) atomicAdd(&g_cnt[__ldg(row + e)], 1);
}

// Scan of PADDED counts p_i = (c_i+1)&~1  (rows start 16B-aligned in g_csr).
__global__ void __launch_bounds__(SCAN_BLK) k_scan1()
{
    __shared__ int s[SCAN_BLK];
    int t = threadIdx.x;
    int i = blockIdx.x * SCAN_BLK + t;
    int c = (i < N_NODES) ? g_cnt[i] : 0;
    int v = (c + 1) & ~1;                 // padded degree
    s[t] = v;
    __syncthreads();
    #pragma unroll
    for (int off = 1; off < SCAN_BLK; off <<= 1) {
        int add = (t >= off) ? s[t - off] : 0;
        __syncthreads();
        s[t] += add;
        __syncthreads();
    }
    if (i < N_NODES) g_rowstart[i] = s[t] - v;           // exclusive in-block
    if (t == SCAN_BLK - 1) g_blksums[blockIdx.x] = s[t]; // block total
}

__global__ void __launch_bounds__(256) k_scan2()
{
    __shared__ int s[256];
    int t = threadIdx.x;
    int v = (t < N_SCAN_BLKS) ? g_blksums[t] : 0;
    s[t] = v;
    __syncthreads();
    #pragma unroll
    for (int off = 1; off < 256; off <<= 1) {
        int add = (t >= off) ? s[t - off] : 0;
        __syncthreads();
        s[t] += add;
        __syncthreads();
    }
    if (t < N_SCAN_BLKS) g_blksums[t] = s[t] - v;        // exclusive
}

// Finalize offsets; init cursors; pack (start,cnt); write w=0 pad slots.
__global__ void k_scan3()
{
    int i = blockIdx.x * blockDim.x + threadIdx.x;
    if (i >= N_NODES) return;
    int v = g_rowstart[i] + g_blksums[i >> 10];
    int c = g_cnt[i];
    g_cursor[i] = v;
    g_hdr[i]    = make_int2(v, c);
    if (c & 1) g_csr[v + c] = make_int2(0, 0);           // col=0, w=0 (harmless)
}

__global__ void __launch_bounds__(256)
k_fill(const int* __restrict__ row, const int* __restrict__ col,
       const float* __restrict__ w)
{
    int e = blockIdx.x * blockDim.x + threadIdx.x;
    if (e >= N_EDGES) return;
    int r   = __ldg(row + e);
    int pos = atomicAdd(&g_cursor[r], 1);
    g_csr[pos] = make_int2(__ldg(col + e), __float_as_int(__ldg(w + e)));
}

// ---------------------------------------------------------------------------
// Gather SpMM: 2 rows per warp, 16 lanes per row, 4 dims (half4 = uint2) per
// lane. 0.75 LDG warp-instr per edge; fp16 src halves sector traffic.
// Accumulation fp32; out fp32.
// ---------------------------------------------------------------------------
__device__ __forceinline__ void fma_edge(float& ax, float& ay, float& az,
                                         float& aw, uint2 u, float w)
{
    __half2 h0 = *reinterpret_cast<__half2*>(&u.x);
    __half2 h1 = *reinterpret_cast<__half2*>(&u.y);
    float2 a = __half22float2(h0);
    float2 b = __half22float2(h1);
    ax += w * a.x; ay += w * a.y; az += w * b.x; aw += w * b.y;
}

template<int LAYER>
__global__ void __launch_bounds__(256)
k_gather(float4* __restrict__ out)
{
    int tid  = blockIdx.x * blockDim.x + threadIdx.x;
    int gw   = tid >> 5;
    int lane = threadIdx.x & 31;
    int half = lane >> 4;
    int sub  = lane & 15;
    int row  = gw * 2 + half;
    if (row >= N_NODES) return;

    const uint2* __restrict__ src =
        (LAYER == 0) ? g_src : (LAYER == 1) ? g_l1h : g_l2h;

    int2 hdr = __ldg(&g_hdr[row]);
    const int start = hdr.x;
    const int pend  = start + ((hdr.y + 1) & ~1);        // padded end (even)
    const int4* csr4 = reinterpret_cast<const int4*>(g_csr);

    float ax = 0.f, ay = 0.f, az = 0.f, aw = 0.f;
    int j = start;

    // 8-edge batches: 4 int4 meta + 8 uint2 src loads in flight per half.
    for (; j + 8 <= pend; j += 8) {
        int4 m0 = __ldg(csr4 + (j >> 1) + 0);
        int4 m1 = __ldg(csr4 + (j >> 1) + 1);
        int4 m2 = __ldg(csr4 + (j >> 1) + 2);
        int4 m3 = __ldg(csr4 + (j >> 1) + 3);
        uint2 v0 = __ldg(src + (size_t)m0.x * 16 + sub);
        uint2 v1 = __ldg(src + (size_t)m0.z * 16 + sub);
        uint2 v2 = __ldg(src + (size_t)m1.x * 16 + sub);
        uint2 v3 = __ldg(src + (size_t)m1.z * 16 + sub);
        uint2 v4 = __ldg(src + (size_t)m2.x * 16 + sub);
        uint2 v5 = __ldg(src + (size_t)m2.z * 16 + sub);
        uint2 v6 = __ldg(src + (size_t)m3.x * 16 + sub);
        uint2 v7 = __ldg(src + (size_t)m3.z * 16 + sub);
        fma_edge(ax, ay, az, aw, v0, __int_as_float(m0.y));
        fma_edge(ax, ay, az, aw, v1, __int_as_float(m0.w));
        fma_edge(ax, ay, az, aw, v2, __int_as_float(m1.y));
        fma_edge(ax, ay, az, aw, v3, __int_as_float(m1.w));
        fma_edge(ax, ay, az, aw, v4, __int_as_float(m2.y));
        fma_edge(ax, ay, az, aw, v5, __int_as_float(m2.w));
        fma_edge(ax, ay, az, aw, v6, __int_as_float(m3.y));
        fma_edge(ax, ay, az, aw, v7, __int_as_float(m3.w));
    }
    if (j + 4 <= pend) {
        int4 m0 = __ldg(csr4 + (j >> 1) + 0);
        int4 m1 = __ldg(csr4 + (j >> 1) + 1);
        uint2 v0 = __ldg(src + (size_t)m0.x * 16 + sub);
        uint2 v1 = __ldg(src + (size_t)m0.z * 16 + sub);
        uint2 v2 = __ldg(src + (size_t)m1.x * 16 + sub);
        uint2 v3 = __ldg(src + (size_t)m1.z * 16 + sub);
        fma_edge(ax, ay, az, aw, v0, __int_as_float(m0.y));
        fma_edge(ax, ay, az, aw, v1, __int_as_float(m0.w));
        fma_edge(ax, ay, az, aw, v2, __int_as_float(m1.y));
        fma_edge(ax, ay, az, aw, v3, __int_as_float(m1.w));
        j += 4;
    }
    if (j + 2 <= pend) {
        int4 m = __ldg(csr4 + (j >> 1));
        uint2 v0 = __ldg(src + (size_t)m.x * 16 + sub);
        uint2 v1 = __ldg(src + (size_t)m.z * 16 + sub);
        fma_edge(ax, ay, az, aw, v0, __int_as_float(m.y));
        fma_edge(ax, ay, az, aw, v1, __int_as_float(m.w));
    }

    const size_t o = (size_t)row * 16 + sub;
    if (LAYER == 0) {
        __half2 h0 = __floats2half2_rn(ax, ay);
        __half2 h1 = __floats2half2_rn(az, aw);
        uint2 u;
        u.x = *reinterpret_cast<unsigned*>(&h0);
        u.y = *reinterpret_cast<unsigned*>(&h1);
        g_l1h[o] = u;                                    // src of L1
        out[o] = make_float4(ax, ay, az, aw);            // l1 fp32, undivided
    } else if (LAYER == 1) {
        __half2 h0 = __floats2half2_rn(ax, ay);
        __half2 h1 = __floats2half2_rn(az, aw);
        uint2 u;
        u.x = *reinterpret_cast<unsigned*>(&h0);
        u.y = *reinterpret_cast<unsigned*>(&h1);
        g_l2h[o] = u;                                    // src of L2 (+final sum)
    } else {
        float4 l1 = out[o];
        uint2  u2 = g_l2h[o];
        __half2 h0 = *reinterpret_cast<__half2*>(&u2.x);
        __half2 h1 = *reinterpret_cast<__half2*>(&u2.y);
        float2 p = __half22float2(h0);
        float2 q = __half22float2(h1);
        const float inv3 = 1.0f / 3.0f;
        out[o] = make_float4((l1.x + p.x + ax) * inv3,
                             (l1.y + p.y + ay) * inv3,
                             (l1.z + q.x + az) * inv3,
                             (l1.w + q.y + aw) * inv3);
    }
}

// ---------------------------------------------------------------------------
// Launch. Inputs (metadata order):
//   d_in[0] user_emb f32 [100000*64]   d_in[1] item_emb f32 [100000*64]
//   d_in[2] edge_w   f32 [3.2M]        d_in[3] edge_row i32   d_in[4] edge_col i32
// d_out: f32 [200000*64] = (l1+l2+l3)/3.
// ---------------------------------------------------------------------------
extern "C" void kernel_launch(void* const* d_in, const int* in_sizes, int n_in,
                              void* d_out, int out_size)
{
    const float4* user = (const float4*)d_in[0];
    const float4* item = (const float4*)d_in[1];
    const float*  ew   = (const float*)d_in[2];
    const int*    erow = (const int*)d_in[3];
    const int*    ecol = (const int*)d_in[4];
    float4*       out  = (float4*)d_out;

    const int BLK = 256;
    const int grid_vec    = (VEC_TOTAL + BLK - 1) / BLK;          // 12500
    const int grid_nodes  = (N_NODES + BLK - 1) / BLK;            // 782
    const int grid_edges  = (N_EDGES + BLK - 1) / BLK;            // 12500
    const int grid_gather = ((N_NODES / 2) * 32 + BLK - 1) / BLK; // 12500

    // fp16 input conversion + CSR build (once; reused by all 3 layers)
    k_init <<<grid_vec, BLK>>>(user, item);
    k_zero <<<grid_nodes, BLK>>>();
    k_count<<<grid_edges, BLK>>>(erow);
    k_scan1<<<N_SCAN_BLKS, SCAN_BLK>>>();
    k_scan2<<<1, 256>>>();
    k_scan3<<<grid_nodes, BLK>>>();
    k_fill <<<grid_edges, BLK>>>(erow, ecol, ew);

    // 3 pull-style SpMM layers
    k_gather<0><<<grid_gather, BLK>>>(out);
    k_gather<1><<<grid_gather, BLK>>>(out);
    k_gather<2><<<grid_gather, BLK>>>(out);
}